// round 14
// baseline (speedup 1.0000x reference)
#include <cuda_runtime.h>
#include <cuda_bf16.h>
#include <cstdint>

#define N_NODES 50000
#define N_EDGES 600000
#define DIM     128
#define MAXDEG  64               // padded CSR row; Poisson(12) max over 50k ~33
#define NODE_BATCH 2

// ----- scratch (allocation-free __device__ globals; zero-init at load) -----
// INVARIANT at entry of every kernel_launch call: g_deg == 0 (first call:
// static zero-init; later calls: fused kernel zeroes each node's entry after
// consuming it). g_work is reset by kernel1 each call before fused runs.
__device__ int   g_deg[N_NODES];
__device__ int2  g_pidx[N_NODES * MAXDEG]; // padded rows: {src node, edge id}
__device__ int   g_work;                   // dynamic node queue (batched)

// ---------------------------------------------------------------------------
// Launch 1: fused histogram + direct scatter into padded CSR rows.
// rank from the atomic IS the final slot: pidx[dst*64 + rank] = {src, e}.
// Also resets the work queue for this call's fused kernel.
// ---------------------------------------------------------------------------
__global__ void build_kernel(const int* __restrict__ src,
                             const int* __restrict__ dst, int n_edges) {
    if (blockIdx.x == 0 && threadIdx.x == 0) g_work = 0;

    int base = (blockIdx.x * blockDim.x + threadIdx.x) * 4;
    if (base + 4 <= n_edges) {
        int4 d = *(const int4*)(dst + base);
        int4 s = *(const int4*)(src + base);
        int r0 = atomicAdd(&g_deg[d.x], 1);
        int r1 = atomicAdd(&g_deg[d.y], 1);
        int r2 = atomicAdd(&g_deg[d.z], 1);
        int r3 = atomicAdd(&g_deg[d.w], 1);
        g_pidx[(d.x << 6) + r0] = make_int2(s.x, base);
        g_pidx[(d.y << 6) + r1] = make_int2(s.y, base + 1);
        g_pidx[(d.z << 6) + r2] = make_int2(s.z, base + 2);
        g_pidx[(d.w << 6) + r3] = make_int2(s.w, base + 3);
    } else {
        for (int e = base; e < n_edges; e++) {
            int dd = dst[e];
            int r = atomicAdd(&g_deg[dd], 1);
            g_pidx[(dd << 6) + r] = make_int2(src[e], e);
        }
    }
}

// ---------------------------------------------------------------------------
// Launch 2: fused per-node kernel, 16-lane sub-warp edges, per-node
// constants staged in shared memory (5 CTAs/SM). No max subtraction
// (shift-invariant; validated rel_err 1.5e-7). Zeroes g_deg[node] after
// reading it to restore the cross-call invariant.
// ---------------------------------------------------------------------------
__global__ void __launch_bounds__(256, 5)
fused_node_kernel(const float* __restrict__ h_v,
                  const float* __restrict__ h_d,
                  const float* __restrict__ W_pi,
                  const float* __restrict__ W_M,
                  float*       __restrict__ out,
                  int n_nodes)
{
    __shared__ float4 s_c1[8][32];   // per-warp: fd * W_pi
    __shared__ float4 s_c2[8][32];   // per-warp: fd * W_M[0:128]
    __shared__ float4 s_w2[32];      // block: W_M[128:256]

    int lane = threadIdx.x & 31;
    int w    = threadIdx.x >> 5;
    int sub  = lane & 15;            // position within half-warp
    int grp  = lane >> 4;            // which edge of the pair

    if (threadIdx.x < 32)
        s_w2[threadIdx.x] = __ldg((const float4*)(W_M + DIM) + threadIdx.x);
    __syncthreads();

    const float4* __restrict__ hv4 = (const float4*)h_v;
    const float4* __restrict__ hd4 = (const float4*)h_d;

    while (true) {
        int base_node;
        if (lane == 0) base_node = atomicAdd(&g_work, NODE_BATCH);
        base_node = __shfl_sync(0xFFFFFFFFu, base_node, 0);
        if (base_node >= n_nodes) break;
        int lim = min(base_node + NODE_BATCH, n_nodes);

        for (int node = base_node; node < lim; node++) {
            int deg = g_deg[node];            // broadcast load
            __syncwarp();
            if (lane == 0) g_deg[node] = 0;   // restore invariant
            int beg = node << 6;              // padded CSR row base

            float4 accl = make_float4(0.f, 0.f, 0.f, 0.f);
            float4 acch = make_float4(0.f, 0.f, 0.f, 0.f);
            float sum = 0.f;

            if (deg > 0) {
                // stage per-node constants in smem
                __syncwarp();
                {
                    float4 fd = hv4[(size_t)node * 32 + lane];
                    float4 wp = __ldg((const float4*)W_pi + lane);
                    float4 w1 = __ldg((const float4*)W_M + lane);
                    s_c1[w][lane] = make_float4(fd.x*wp.x, fd.y*wp.y, fd.z*wp.z, fd.w*wp.w);
                    s_c2[w][lane] = make_float4(fd.x*w1.x, fd.y*w1.y, fd.z*w1.z, fd.w*w1.w);
                }
                __syncwarp();

                for (int cb = 0; cb < deg; cb += 32) {
                    int cnt = min(32, deg - cb);
                    int2 p = (lane < cnt) ? g_pidx[beg + cb + lane]
                                          : make_int2(0, 0);

                    for (int i = 0; i < cnt; i += 2) {
                        int idx   = i + grp;
                        bool valid = (idx < cnt);
                        int srcl  = valid ? idx : i;      // i always valid
                        int s = __shfl_sync(0xFFFFFFFFu, p.x, srcl);
                        int e = __shfl_sync(0xFFFFFFFFu, p.y, srcl);

                        const float4* fsr = hv4 + (size_t)s * 32;
                        const float4* hdr = hd4 + (size_t)e * 32;
                        float4 fsl = fsr[sub], fsh = fsr[16 + sub];
                        float4 hdl = hdr[sub], hdh = hdr[16 + sub];

                        float4 c1l = s_c1[w][sub], c1h = s_c1[w][16 + sub];
                        float4 c2l = s_c2[w][sub], c2h = s_c2[w][16 + sub];
                        float4 w2l = s_w2[sub],    w2h = s_w2[16 + sub];

                        float a1 = fsl.x*hdl.x*c1l.x + fsl.y*hdl.y*c1l.y
                                 + fsl.z*hdl.z*c1l.z + fsl.w*hdl.w*c1l.w
                                 + fsh.x*hdh.x*c1h.x + fsh.y*hdh.y*c1h.y
                                 + fsh.z*hdh.z*c1h.z + fsh.w*hdh.w*c1h.w;
                        float a2 = fsl.x*c2l.x + fsl.y*c2l.y + fsl.z*c2l.z + fsl.w*c2l.w
                                 + fsh.x*c2h.x + fsh.y*c2h.y + fsh.z*c2h.z + fsh.w*c2h.w
                                 + hdl.x*w2l.x + hdl.y*w2l.y + hdl.z*w2l.z + hdl.w*w2l.w
                                 + hdh.x*w2h.x + hdh.y*w2h.y + hdh.z*w2h.z + hdh.w*w2h.w;

                        // 4-step butterfly within each half-warp (serves both edges)
                        #pragma unroll
                        for (int o = 8; o; o >>= 1) {
                            a1 += __shfl_xor_sync(0xFFFFFFFFu, a1, o);
                            a2 += __shfl_xor_sync(0xFFFFFFFFu, a2, o);
                        }

                        float ev = __expf(a1 * (1.0f / (1.0f + __expf(-a2))));
                        if (!valid) ev = 0.f;
                        sum += ev;
                        accl.x += fsl.x * ev; accl.y += fsl.y * ev;
                        accl.z += fsl.z * ev; accl.w += fsl.w * ev;
                        acch.x += fsh.x * ev; acch.y += fsh.y * ev;
                        acch.z += fsh.z * ev; acch.w += fsh.w * ev;
                    }
                }

                // combine the two half-warp partials
                sum    += __shfl_xor_sync(0xFFFFFFFFu, sum,    16);
                accl.x += __shfl_xor_sync(0xFFFFFFFFu, accl.x, 16);
                accl.y += __shfl_xor_sync(0xFFFFFFFFu, accl.y, 16);
                accl.z += __shfl_xor_sync(0xFFFFFFFFu, accl.z, 16);
                accl.w += __shfl_xor_sync(0xFFFFFFFFu, accl.w, 16);
                acch.x += __shfl_xor_sync(0xFFFFFFFFu, acch.x, 16);
                acch.y += __shfl_xor_sync(0xFFFFFFFFu, acch.y, 16);
                acch.z += __shfl_xor_sync(0xFFFFFFFFu, acch.z, 16);
                acch.w += __shfl_xor_sync(0xFFFFFFFFu, acch.w, 16);

                float inv = 1.0f / sum;
                accl.x *= inv; accl.y *= inv; accl.z *= inv; accl.w *= inv;
                acch.x *= inv; acch.y *= inv; acch.z *= inv; acch.w *= inv;
            }

            if (grp == 0) {
                float4* orow = (float4*)out + (size_t)node * 32;
                orow[sub]      = accl;
                orow[16 + sub] = acch;
            }
        }
    }
}

// ---------------------------------------------------------------------------
// Launch
// inputs: 0=h_v [N,128] f32, 1=h_d [E,128] f32, 2=W_pi [128,1] f32,
//         3=W_M [256,1] f32, 4=src [E] i32, 5=dst [E] i32 ; out [N,128] f32
// ---------------------------------------------------------------------------
extern "C" void kernel_launch(void* const* d_in, const int* in_sizes, int n_in,
                              void* d_out, int out_size)
{
    const float* h_v  = (const float*)d_in[0];
    const float* h_d  = (const float*)d_in[1];
    const float* W_pi = (const float*)d_in[2];
    const float* W_M  = (const float*)d_in[3];
    const int*   src  = (const int*)d_in[4];
    const int*   dst  = (const int*)d_in[5];
    float*       out  = (float*)d_out;

    int n_nodes = in_sizes[0] / DIM;
    int n_edges = in_sizes[1] / DIM;
    int quad_blocks = (n_edges / 4 + 255) / 256 + 1;

    build_kernel<<<quad_blocks, 256>>>(src, dst, n_edges);
    fused_node_kernel<<<740, 256>>>(h_v, h_d, W_pi, W_M, out, n_nodes);
}

// round 15
// speedup vs baseline: 1.0121x; 1.0121x over previous
#include <cuda_runtime.h>
#include <cuda_bf16.h>
#include <cstdint>

#define N_NODES 50000
#define N_EDGES 600000
#define DIM     128
#define SCAN_BLOCKS 256          // >= ceil(N_NODES/256) = 196
#define NODE_BATCH 2

// ----- scratch (allocation-free __device__ globals; zero-init at load) -----
// INVARIANT: g_deg == 0, g_scan_flag == 0 at entry of every kernel_launch
// call. First call: static zero-init. Later calls: scan_kernel re-zeros
// g_deg + g_work, scatter_perm re-zeros g_scan_flag.
__device__ int   g_deg[N_NODES];
__device__ int   g_off[N_NODES + 1];
__device__ int   g_rank[N_EDGES];      // intra-segment rank of each edge
__device__ int2  g_pidx[N_EDGES];      // CSR-ordered {src node, original edge id}
__device__ int   g_scan_flag[SCAN_BLOCKS];
__device__ int   g_scan_agg[SCAN_BLOCKS];
__device__ int   g_scan_inc[SCAN_BLOCKS];
__device__ int   g_work;               // dynamic node queue (batched)

// ---------------------------------------------------------------------------
// Launch 1: histogram + intra-segment rank; 8 edges/thread for MLP
// ---------------------------------------------------------------------------
__global__ void hist_kernel(const int* __restrict__ dst, int n_edges) {
    int base = (blockIdx.x * blockDim.x + threadIdx.x) * 8;
    if (base + 8 <= n_edges) {
        int4 dA = *(const int4*)(dst + base);
        int4 dB = *(const int4*)(dst + base + 4);
        int r0 = atomicAdd(&g_deg[dA.x], 1);
        int r1 = atomicAdd(&g_deg[dA.y], 1);
        int r2 = atomicAdd(&g_deg[dA.z], 1);
        int r3 = atomicAdd(&g_deg[dA.w], 1);
        int r4 = atomicAdd(&g_deg[dB.x], 1);
        int r5 = atomicAdd(&g_deg[dB.y], 1);
        int r6 = atomicAdd(&g_deg[dB.z], 1);
        int r7 = atomicAdd(&g_deg[dB.w], 1);
        *(int4*)(g_rank + base)     = make_int4(r0, r1, r2, r3);
        *(int4*)(g_rank + base + 4) = make_int4(r4, r5, r6, r7);
    } else {
        for (int e = base; e < n_edges; e++)
            g_rank[e] = atomicAdd(&g_deg[dst[e]], 1);
    }
}

// ---------------------------------------------------------------------------
// Launch 2: single-pass exclusive scan (decoupled lookback); re-zeros g_deg
// and g_work.
// ---------------------------------------------------------------------------
__global__ void __launch_bounds__(256)
scan_kernel(int n_nodes, int n_edges) {
    int b = blockIdx.x, t = threadIdx.x;
    int idx = b * 256 + t;
    int lane = t & 31, w = t >> 5;

    int v = (idx < n_nodes) ? g_deg[idx] : 0;

    int x = v;
    #pragma unroll
    for (int o = 1; o < 32; o <<= 1) {
        int y = __shfl_up_sync(0xFFFFFFFFu, x, o);
        if (lane >= o) x += y;
    }
    __shared__ int wsum[8];
    if (lane == 31) wsum[w] = x;
    __syncthreads();
    if (w == 0) {
        int s = (lane < 8) ? wsum[lane] : 0;
        #pragma unroll
        for (int o = 1; o < 8; o <<= 1) {
            int y = __shfl_up_sync(0xFFFFFFFFu, s, o);
            if (lane >= o) s += y;
        }
        if (lane < 8) wsum[lane] = s;
    }
    __syncthreads();
    int incl = x + ((w > 0) ? wsum[w - 1] : 0);
    int block_total = wsum[7];

    __shared__ int s_prefix;
    if (t == 0) {
        if (b == 0) {
            g_scan_inc[0] = block_total;
            __threadfence();
            atomicExch(&g_scan_flag[0], 2);
            s_prefix = 0;
        } else {
            g_scan_agg[b] = block_total;
            __threadfence();
            atomicExch(&g_scan_flag[b], 1);
            int sum = 0;
            for (int j = b - 1; j >= 0; j--) {
                int f;
                do { f = atomicAdd(&g_scan_flag[j], 0); } while (f == 0);
                if (f == 2) { sum += atomicAdd(&g_scan_inc[j], 0); break; }
                sum += atomicAdd(&g_scan_agg[j], 0);
            }
            g_scan_inc[b] = sum + block_total;
            __threadfence();
            atomicExch(&g_scan_flag[b], 2);
            s_prefix = sum;
        }
    }
    __syncthreads();

    int excl = s_prefix + incl - v;
    if (idx < n_nodes) {
        g_off[idx] = excl;
        g_deg[idx] = 0;                    // restore invariant
    }
    if (idx == n_nodes) g_off[n_nodes] = n_edges;
    if (idx == 0) g_work = 0;
}

// ---------------------------------------------------------------------------
// Launch 3: atomic-free permutation scatter; 8 edges/thread; re-zeros flags.
// ---------------------------------------------------------------------------
__global__ void __launch_bounds__(256)
scatter_perm_kernel(const int* __restrict__ src,
                    const int* __restrict__ dst, int n_edges) {
    if (blockIdx.x == 0 && threadIdx.x < SCAN_BLOCKS)
        g_scan_flag[threadIdx.x] = 0;

    int base = (blockIdx.x * blockDim.x + threadIdx.x) * 8;
    if (base + 8 <= n_edges) {
        int4 dA = *(const int4*)(dst + base);
        int4 dB = *(const int4*)(dst + base + 4);
        int4 rA = *(const int4*)(g_rank + base);
        int4 rB = *(const int4*)(g_rank + base + 4);
        int4 sA = *(const int4*)(src + base);
        int4 sB = *(const int4*)(src + base + 4);
        int o0 = g_off[dA.x], o1 = g_off[dA.y], o2 = g_off[dA.z], o3 = g_off[dA.w];
        int o4 = g_off[dB.x], o5 = g_off[dB.y], o6 = g_off[dB.z], o7 = g_off[dB.w];
        g_pidx[o0 + rA.x] = make_int2(sA.x, base);
        g_pidx[o1 + rA.y] = make_int2(sA.y, base + 1);
        g_pidx[o2 + rA.z] = make_int2(sA.z, base + 2);
        g_pidx[o3 + rA.w] = make_int2(sA.w, base + 3);
        g_pidx[o4 + rB.x] = make_int2(sB.x, base + 4);
        g_pidx[o5 + rB.y] = make_int2(sB.y, base + 5);
        g_pidx[o6 + rB.z] = make_int2(sB.z, base + 6);
        g_pidx[o7 + rB.w] = make_int2(sB.w, base + 7);
    } else {
        for (int e = base; e < n_edges; e++)
            g_pidx[g_off[dst[e]] + g_rank[e]] = make_int2(src[e], e);
    }
}

// ---------------------------------------------------------------------------
// Launch 4: fused per-node kernel (R13-proven), 16-lane sub-warp edges,
// per-node constants in smem, 5 CTAs/SM; batch g_off loads hoisted.
// No max subtraction (shift-invariant; validated rel_err 1.5e-7).
// ---------------------------------------------------------------------------
__global__ void __launch_bounds__(256, 5)
fused_node_kernel(const float* __restrict__ h_v,
                  const float* __restrict__ h_d,
                  const float* __restrict__ W_pi,
                  const float* __restrict__ W_M,
                  float*       __restrict__ out,
                  int n_nodes)
{
    __shared__ float4 s_c1[8][32];   // per-warp: fd * W_pi
    __shared__ float4 s_c2[8][32];   // per-warp: fd * W_M[0:128]
    __shared__ float4 s_w2[32];      // block: W_M[128:256]

    int lane = threadIdx.x & 31;
    int w    = threadIdx.x >> 5;
    int sub  = lane & 15;            // position within half-warp
    int grp  = lane >> 4;            // which edge of the pair

    if (threadIdx.x < 32)
        s_w2[threadIdx.x] = __ldg((const float4*)(W_M + DIM) + threadIdx.x);
    __syncthreads();

    const float4* __restrict__ hv4 = (const float4*)h_v;
    const float4* __restrict__ hd4 = (const float4*)h_d;

    while (true) {
        int base_node;
        if (lane == 0) base_node = atomicAdd(&g_work, NODE_BATCH);
        base_node = __shfl_sync(0xFFFFFFFFu, base_node, 0);
        if (base_node >= n_nodes) break;
        int lim = min(base_node + NODE_BATCH, n_nodes);

        // hoist all batch offsets (independent loads, issued together)
        int off0 = g_off[base_node];
        int off1 = g_off[base_node + 1];
        int off2 = (lim > base_node + 1) ? g_off[base_node + 2] : off1;

        for (int node = base_node; node < lim; node++) {
            int beg = (node == base_node) ? off0 : off1;
            int nxt = (node == base_node) ? off1 : off2;
            int deg = nxt - beg;

            float4 accl = make_float4(0.f, 0.f, 0.f, 0.f);
            float4 acch = make_float4(0.f, 0.f, 0.f, 0.f);
            float sum = 0.f;

            if (deg > 0) {
                // stage per-node constants in smem
                __syncwarp();
                {
                    float4 fd = hv4[(size_t)node * 32 + lane];
                    float4 wp = __ldg((const float4*)W_pi + lane);
                    float4 w1 = __ldg((const float4*)W_M + lane);
                    s_c1[w][lane] = make_float4(fd.x*wp.x, fd.y*wp.y, fd.z*wp.z, fd.w*wp.w);
                    s_c2[w][lane] = make_float4(fd.x*w1.x, fd.y*w1.y, fd.z*w1.z, fd.w*w1.w);
                }
                __syncwarp();

                for (int cb = 0; cb < deg; cb += 32) {
                    int cnt = min(32, deg - cb);
                    int2 p = (lane < cnt) ? g_pidx[beg + cb + lane]
                                          : make_int2(0, 0);

                    for (int i = 0; i < cnt; i += 2) {
                        int idx   = i + grp;
                        bool valid = (idx < cnt);
                        int srcl  = valid ? idx : i;      // i always valid
                        int s = __shfl_sync(0xFFFFFFFFu, p.x, srcl);
                        int e = __shfl_sync(0xFFFFFFFFu, p.y, srcl);

                        const float4* fsr = hv4 + (size_t)s * 32;
                        const float4* hdr = hd4 + (size_t)e * 32;
                        float4 fsl = fsr[sub], fsh = fsr[16 + sub];
                        float4 hdl = hdr[sub], hdh = hdr[16 + sub];

                        float4 c1l = s_c1[w][sub], c1h = s_c1[w][16 + sub];
                        float4 c2l = s_c2[w][sub], c2h = s_c2[w][16 + sub];
                        float4 w2l = s_w2[sub],    w2h = s_w2[16 + sub];

                        float a1 = fsl.x*hdl.x*c1l.x + fsl.y*hdl.y*c1l.y
                                 + fsl.z*hdl.z*c1l.z + fsl.w*hdl.w*c1l.w
                                 + fsh.x*hdh.x*c1h.x + fsh.y*hdh.y*c1h.y
                                 + fsh.z*hdh.z*c1h.z + fsh.w*hdh.w*c1h.w;
                        float a2 = fsl.x*c2l.x + fsl.y*c2l.y + fsl.z*c2l.z + fsl.w*c2l.w
                                 + fsh.x*c2h.x + fsh.y*c2h.y + fsh.z*c2h.z + fsh.w*c2h.w
                                 + hdl.x*w2l.x + hdl.y*w2l.y + hdl.z*w2l.z + hdl.w*w2l.w
                                 + hdh.x*w2h.x + hdh.y*w2h.y + hdh.z*w2h.z + hdh.w*w2h.w;

                        // 4-step butterfly within each half-warp (serves both edges)
                        #pragma unroll
                        for (int o = 8; o; o >>= 1) {
                            a1 += __shfl_xor_sync(0xFFFFFFFFu, a1, o);
                            a2 += __shfl_xor_sync(0xFFFFFFFFu, a2, o);
                        }

                        float ev = __expf(a1 * (1.0f / (1.0f + __expf(-a2))));
                        if (!valid) ev = 0.f;
                        sum += ev;
                        accl.x += fsl.x * ev; accl.y += fsl.y * ev;
                        accl.z += fsl.z * ev; accl.w += fsl.w * ev;
                        acch.x += fsh.x * ev; acch.y += fsh.y * ev;
                        acch.z += fsh.z * ev; acch.w += fsh.w * ev;
                    }
                }

                // combine the two half-warp partials
                sum    += __shfl_xor_sync(0xFFFFFFFFu, sum,    16);
                accl.x += __shfl_xor_sync(0xFFFFFFFFu, accl.x, 16);
                accl.y += __shfl_xor_sync(0xFFFFFFFFu, accl.y, 16);
                accl.z += __shfl_xor_sync(0xFFFFFFFFu, accl.z, 16);
                accl.w += __shfl_xor_sync(0xFFFFFFFFu, accl.w, 16);
                acch.x += __shfl_xor_sync(0xFFFFFFFFu, acch.x, 16);
                acch.y += __shfl_xor_sync(0xFFFFFFFFu, acch.y, 16);
                acch.z += __shfl_xor_sync(0xFFFFFFFFu, acch.z, 16);
                acch.w += __shfl_xor_sync(0xFFFFFFFFu, acch.w, 16);

                float inv = 1.0f / sum;
                accl.x *= inv; accl.y *= inv; accl.z *= inv; accl.w *= inv;
                acch.x *= inv; acch.y *= inv; acch.z *= inv; acch.w *= inv;
            }

            if (grp == 0) {
                float4* orow = (float4*)out + (size_t)node * 32;
                orow[sub]      = accl;
                orow[16 + sub] = acch;
            }
        }
    }
}

// ---------------------------------------------------------------------------
// Launch
// inputs: 0=h_v [N,128] f32, 1=h_d [E,128] f32, 2=W_pi [128,1] f32,
//         3=W_M [256,1] f32, 4=src [E] i32, 5=dst [E] i32 ; out [N,128] f32
// ---------------------------------------------------------------------------
extern "C" void kernel_launch(void* const* d_in, const int* in_sizes, int n_in,
                              void* d_out, int out_size)
{
    const float* h_v  = (const float*)d_in[0];
    const float* h_d  = (const float*)d_in[1];
    const float* W_pi = (const float*)d_in[2];
    const float* W_M  = (const float*)d_in[3];
    const int*   src  = (const int*)d_in[4];
    const int*   dst  = (const int*)d_in[5];
    float*       out  = (float*)d_out;

    int n_nodes = in_sizes[0] / DIM;
    int n_edges = in_sizes[1] / DIM;
    int node_blocks = (n_nodes + 255) / 256;
    int oct_blocks  = (n_edges / 8 + 255) / 256 + 1;

    hist_kernel<<<oct_blocks, 256>>>(dst, n_edges);
    scan_kernel<<<node_blocks, 256>>>(n_nodes, n_edges);
    scatter_perm_kernel<<<oct_blocks, 256>>>(src, dst, n_edges);
    fused_node_kernel<<<740, 256>>>(h_v, h_d, W_pi, W_M, out, n_nodes);
}

// round 16
// speedup vs baseline: 1.4369x; 1.4198x over previous
#include <cuda_runtime.h>
#include <cuda_bf16.h>
#include <cstdint>

#define N_NODES 50000
#define N_EDGES 600000
#define DIM     128
#define SCAN_BLOCKS 256          // >= ceil(N_NODES/256) = 196
#define NODE_BATCH 2

// ----- scratch (allocation-free __device__ globals; zero-init at load) -----
// INVARIANT: g_deg == 0, g_scan_flag == 0, g_work == 0 at entry of every
// kernel_launch call. First call: static zero-init. Later calls: scan_kernel
// re-zeros g_deg + g_work, scatter_perm re-zeros g_scan_flag.
__device__ int   g_deg[N_NODES];
__device__ int   g_off[N_NODES + 1];
__device__ int   g_rank[N_EDGES];      // intra-segment rank of each edge
__device__ int2  g_pidx[N_EDGES];      // CSR-ordered {src node, original edge id}
__device__ int   g_scan_flag[SCAN_BLOCKS];
__device__ int   g_scan_agg[SCAN_BLOCKS];
__device__ int   g_scan_inc[SCAN_BLOCKS];
__device__ int   g_work;               // dynamic node queue (batched)

// ---------------------------------------------------------------------------
// Launch 1: histogram + record intra-segment rank; int4 loads for dst
// ---------------------------------------------------------------------------
__global__ void hist_kernel(const int* __restrict__ dst, int n_edges) {
    int base = (blockIdx.x * blockDim.x + threadIdx.x) * 4;
    if (base + 4 <= n_edges) {
        int4 d = *(const int4*)(dst + base);
        int r0 = atomicAdd(&g_deg[d.x], 1);
        int r1 = atomicAdd(&g_deg[d.y], 1);
        int r2 = atomicAdd(&g_deg[d.z], 1);
        int r3 = atomicAdd(&g_deg[d.w], 1);
        *(int4*)(g_rank + base) = make_int4(r0, r1, r2, r3);
    } else {
        for (int e = base; e < n_edges; e++)
            g_rank[e] = atomicAdd(&g_deg[dst[e]], 1);
    }
}

// ---------------------------------------------------------------------------
// Launch 2: single-pass exclusive scan (decoupled lookback); re-zeros g_deg
// and g_work.
// ---------------------------------------------------------------------------
__global__ void __launch_bounds__(256)
scan_kernel(int n_nodes, int n_edges) {
    int b = blockIdx.x, t = threadIdx.x;
    int idx = b * 256 + t;
    int lane = t & 31, w = t >> 5;

    int v = (idx < n_nodes) ? g_deg[idx] : 0;

    int x = v;
    #pragma unroll
    for (int o = 1; o < 32; o <<= 1) {
        int y = __shfl_up_sync(0xFFFFFFFFu, x, o);
        if (lane >= o) x += y;
    }
    __shared__ int wsum[8];
    if (lane == 31) wsum[w] = x;
    __syncthreads();
    if (w == 0) {
        int s = (lane < 8) ? wsum[lane] : 0;
        #pragma unroll
        for (int o = 1; o < 8; o <<= 1) {
            int y = __shfl_up_sync(0xFFFFFFFFu, s, o);
            if (lane >= o) s += y;
        }
        if (lane < 8) wsum[lane] = s;
    }
    __syncthreads();
    int incl = x + ((w > 0) ? wsum[w - 1] : 0);
    int block_total = wsum[7];

    __shared__ int s_prefix;
    if (t == 0) {
        if (b == 0) {
            g_scan_inc[0] = block_total;
            __threadfence();
            atomicExch(&g_scan_flag[0], 2);
            s_prefix = 0;
        } else {
            g_scan_agg[b] = block_total;
            __threadfence();
            atomicExch(&g_scan_flag[b], 1);
            int sum = 0;
            for (int j = b - 1; j >= 0; j--) {
                int f;
                do { f = atomicAdd(&g_scan_flag[j], 0); } while (f == 0);
                if (f == 2) { sum += atomicAdd(&g_scan_inc[j], 0); break; }
                sum += atomicAdd(&g_scan_agg[j], 0);
            }
            g_scan_inc[b] = sum + block_total;
            __threadfence();
            atomicExch(&g_scan_flag[b], 2);
            s_prefix = sum;
        }
    }
    __syncthreads();

    int excl = s_prefix + incl - v;
    if (idx < n_nodes) {
        g_off[idx] = excl;
        g_deg[idx] = 0;                    // restore invariant
    }
    if (idx == n_nodes) g_off[n_nodes] = n_edges;
    if (idx == 0) g_work = 0;
}

// ---------------------------------------------------------------------------
// Launch 3: atomic-free permutation scatter; re-zeros scan flags.
// ---------------------------------------------------------------------------
__global__ void __launch_bounds__(256)
scatter_perm_kernel(const int* __restrict__ src,
                    const int* __restrict__ dst, int n_edges) {
    if (blockIdx.x == 0 && threadIdx.x < SCAN_BLOCKS)
        g_scan_flag[threadIdx.x] = 0;

    int base = (blockIdx.x * blockDim.x + threadIdx.x) * 4;
    if (base + 4 <= n_edges) {
        int4 d = *(const int4*)(dst + base);
        int4 r = *(const int4*)(g_rank + base);
        int4 s = *(const int4*)(src + base);
        int o0 = g_off[d.x], o1 = g_off[d.y], o2 = g_off[d.z], o3 = g_off[d.w];
        g_pidx[o0 + r.x] = make_int2(s.x, base);
        g_pidx[o1 + r.y] = make_int2(s.y, base + 1);
        g_pidx[o2 + r.z] = make_int2(s.z, base + 2);
        g_pidx[o3 + r.w] = make_int2(s.w, base + 3);
    } else {
        for (int e = base; e < n_edges; e++)
            g_pidx[g_off[dst[e]] + g_rank[e]] = make_int2(src[e], e);
    }
}

// ---------------------------------------------------------------------------
// Launch 4 (profiled slot): fused per-node kernel, 16-lane sub-warp edges,
// per-node constants staged in SHARED MEMORY to cut register pressure and
// raise occupancy to 5 CTAs/SM. No max subtraction (shift-invariant;
// validated rel_err 1.5e-7).
// ---------------------------------------------------------------------------
__global__ void __launch_bounds__(256, 5)
fused_node_kernel(const float* __restrict__ h_v,
                  const float* __restrict__ h_d,
                  const float* __restrict__ W_pi,
                  const float* __restrict__ W_M,
                  float*       __restrict__ out,
                  int n_nodes)
{
    __shared__ float4 s_c1[8][32];   // per-warp: fd * W_pi
    __shared__ float4 s_c2[8][32];   // per-warp: fd * W_M[0:128]
    __shared__ float4 s_w2[32];      // block: W_M[128:256]

    int lane = threadIdx.x & 31;
    int w    = threadIdx.x >> 5;
    int sub  = lane & 15;            // position within half-warp
    int grp  = lane >> 4;            // which edge of the pair

    if (threadIdx.x < 32)
        s_w2[threadIdx.x] = __ldg((const float4*)(W_M + DIM) + threadIdx.x);
    __syncthreads();

    const float4* __restrict__ hv4 = (const float4*)h_v;
    const float4* __restrict__ hd4 = (const float4*)h_d;

    while (true) {
        int base_node;
        if (lane == 0) base_node = atomicAdd(&g_work, NODE_BATCH);
        base_node = __shfl_sync(0xFFFFFFFFu, base_node, 0);
        if (base_node >= n_nodes) break;
        int lim = min(base_node + NODE_BATCH, n_nodes);

        int beg = g_off[base_node];
        for (int node = base_node; node < lim; node++) {
            int nxt = g_off[node + 1];
            int deg = nxt - beg;

            float4 accl = make_float4(0.f, 0.f, 0.f, 0.f);
            float4 acch = make_float4(0.f, 0.f, 0.f, 0.f);
            float sum = 0.f;

            if (deg > 0) {
                // stage per-node constants in smem (frees ~24 regs)
                __syncwarp();   // prior node's readers done before overwrite
                {
                    float4 fd = hv4[(size_t)node * 32 + lane];
                    float4 wp = __ldg((const float4*)W_pi + lane);
                    float4 w1 = __ldg((const float4*)W_M + lane);
                    s_c1[w][lane] = make_float4(fd.x*wp.x, fd.y*wp.y, fd.z*wp.z, fd.w*wp.w);
                    s_c2[w][lane] = make_float4(fd.x*w1.x, fd.y*w1.y, fd.z*w1.z, fd.w*w1.w);
                }
                __syncwarp();

                for (int cb = 0; cb < deg; cb += 32) {
                    int cnt = min(32, deg - cb);
                    int2 p = (lane < cnt) ? g_pidx[beg + cb + lane]
                                          : make_int2(0, 0);

                    for (int i = 0; i < cnt; i += 2) {
                        int idx   = i + grp;
                        bool valid = (idx < cnt);
                        int srcl  = valid ? idx : i;      // i always valid
                        int s = __shfl_sync(0xFFFFFFFFu, p.x, srcl);
                        int e = __shfl_sync(0xFFFFFFFFu, p.y, srcl);

                        const float4* fsr = hv4 + (size_t)s * 32;
                        const float4* hdr = hd4 + (size_t)e * 32;
                        float4 fsl = fsr[sub], fsh = fsr[16 + sub];
                        float4 hdl = hdr[sub], hdh = hdr[16 + sub];

                        float4 c1l = s_c1[w][sub], c1h = s_c1[w][16 + sub];
                        float4 c2l = s_c2[w][sub], c2h = s_c2[w][16 + sub];
                        float4 w2l = s_w2[sub],    w2h = s_w2[16 + sub];

                        float a1 = fsl.x*hdl.x*c1l.x + fsl.y*hdl.y*c1l.y
                                 + fsl.z*hdl.z*c1l.z + fsl.w*hdl.w*c1l.w
                                 + fsh.x*hdh.x*c1h.x + fsh.y*hdh.y*c1h.y
                                 + fsh.z*hdh.z*c1h.z + fsh.w*hdh.w*c1h.w;
                        float a2 = fsl.x*c2l.x + fsl.y*c2l.y + fsl.z*c2l.z + fsl.w*c2l.w
                                 + fsh.x*c2h.x + fsh.y*c2h.y + fsh.z*c2h.z + fsh.w*c2h.w
                                 + hdl.x*w2l.x + hdl.y*w2l.y + hdl.z*w2l.z + hdl.w*w2l.w
                                 + hdh.x*w2h.x + hdh.y*w2h.y + hdh.z*w2h.z + hdh.w*w2h.w;

                        // 4-step butterfly within each half-warp (serves both edges)
                        #pragma unroll
                        for (int o = 8; o; o >>= 1) {
                            a1 += __shfl_xor_sync(0xFFFFFFFFu, a1, o);
                            a2 += __shfl_xor_sync(0xFFFFFFFFu, a2, o);
                        }

                        float ev = __expf(a1 * (1.0f / (1.0f + __expf(-a2))));
                        if (!valid) ev = 0.f;
                        sum += ev;
                        accl.x += fsl.x * ev; accl.y += fsl.y * ev;
                        accl.z += fsl.z * ev; accl.w += fsl.w * ev;
                        acch.x += fsh.x * ev; acch.y += fsh.y * ev;
                        acch.z += fsh.z * ev; acch.w += fsh.w * ev;
                    }
                }

                // combine the two half-warp partials (same dims, different edges)
                sum    += __shfl_xor_sync(0xFFFFFFFFu, sum,    16);
                accl.x += __shfl_xor_sync(0xFFFFFFFFu, accl.x, 16);
                accl.y += __shfl_xor_sync(0xFFFFFFFFu, accl.y, 16);
                accl.z += __shfl_xor_sync(0xFFFFFFFFu, accl.z, 16);
                accl.w += __shfl_xor_sync(0xFFFFFFFFu, accl.w, 16);
                acch.x += __shfl_xor_sync(0xFFFFFFFFu, acch.x, 16);
                acch.y += __shfl_xor_sync(0xFFFFFFFFu, acch.y, 16);
                acch.z += __shfl_xor_sync(0xFFFFFFFFu, acch.z, 16);
                acch.w += __shfl_xor_sync(0xFFFFFFFFu, acch.w, 16);

                float inv = 1.0f / sum;
                accl.x *= inv; accl.y *= inv; accl.z *= inv; accl.w *= inv;
                acch.x *= inv; acch.y *= inv; acch.z *= inv; acch.w *= inv;
            }

            if (grp == 0) {
                float4* orow = (float4*)out + (size_t)node * 32;
                orow[sub]      = accl;
                orow[16 + sub] = acch;
            }
            beg = nxt;
        }
    }
}

// ---------------------------------------------------------------------------
// Launch
// inputs: 0=h_v [N,128] f32, 1=h_d [E,128] f32, 2=W_pi [128,1] f32,
//         3=W_M [256,1] f32, 4=src [E] i32, 5=dst [E] i32 ; out [N,128] f32
// ---------------------------------------------------------------------------
extern "C" void kernel_launch(void* const* d_in, const int* in_sizes, int n_in,
                              void* d_out, int out_size)
{
    const float* h_v  = (const float*)d_in[0];
    const float* h_d  = (const float*)d_in[1];
    const float* W_pi = (const float*)d_in[2];
    const float* W_M  = (const float*)d_in[3];
    const int*   src  = (const int*)d_in[4];
    const int*   dst  = (const int*)d_in[5];
    float*       out  = (float*)d_out;

    int n_nodes = in_sizes[0] / DIM;
    int n_edges = in_sizes[1] / DIM;
    int node_blocks = (n_nodes + 255) / 256;
    int quad_blocks = (n_edges / 4 + 255) / 256 + 1;

    hist_kernel<<<quad_blocks, 256>>>(dst, n_edges);
    scan_kernel<<<node_blocks, 256>>>(n_nodes, n_edges);
    scatter_perm_kernel<<<quad_blocks, 256>>>(src, dst, n_edges);
    fused_node_kernel<<<740, 256>>>(h_v, h_d, W_pi, W_M, out, n_nodes);
}